// round 11
// baseline (speedup 1.0000x reference)
#include <cuda_runtime.h>
#include <cuda_bf16.h>
#include <cstdint>

#define NQ 2048
#define NK 4096
#define DIMK 1024

// Split-bf16 operand storage: per (pos, head) one 128B row = hi d0..31 | lo d0..31,
// 16B units permuted u ^= (pos & 7)  (conflict-free ldmatrix).
__device__ uint4 g_K_sw[NK * 8 * 8];   // (pos*8+head)*8 units
__device__ uint4 g_Q_sw[NQ * 8 * 8];

#define LDSM4(r, addr) \
    asm volatile("ldmatrix.sync.aligned.m8n8.x4.shared.b16 {%0,%1,%2,%3}, [%4];" \
        : "=r"((r)[0]),"=r"((r)[1]),"=r"((r)[2]),"=r"((r)[3]) : "r"(addr))

#define MMA_BF16(accp, a, b0, b1) \
    asm volatile("mma.sync.aligned.m16n8k16.row.col.f32.bf16.bf16.f32 " \
        "{%0,%1,%2,%3}, {%4,%5,%6,%7}, {%8,%9}, {%0,%1,%2,%3};" \
        : "+f"((accp)[0]),"+f"((accp)[1]),"+f"((accp)[2]),"+f"((accp)[3]) \
        : "r"((a)[0]),"r"((a)[1]),"r"((a)[2]),"r"((a)[3]), "r"(b0),"r"(b1))

static __device__ __forceinline__ uint32_t smem_u32(const void* p) {
    uint32_t a;
    asm("{ .reg .u64 t; cvta.to.shared.u64 t, %1; cvt.u32.u64 %0, t; }"
        : "=r"(a) : "l"(p));
    return a;
}

static __device__ __forceinline__ void split2(float f0, float f1,
                                              uint32_t& hv, uint32_t& lv) {
    __nv_bfloat16 h0 = __float2bfloat16(f0);
    __nv_bfloat16 h1 = __float2bfloat16(f1);
    __nv_bfloat16 l0 = __float2bfloat16(f0 - __bfloat162float(h0));
    __nv_bfloat16 l1 = __float2bfloat16(f1 - __bfloat162float(h1));
    hv = (uint32_t)__bfloat16_as_ushort(h0) | ((uint32_t)__bfloat16_as_ushort(h1) << 16);
    lv = (uint32_t)__bfloat16_as_ushort(l0) | ((uint32_t)__bfloat16_as_ushort(l1) << 16);
}

// ---------------------------------------------------------------------------
// Tensor-core projection (R10, unchanged): CTA 64M x 64N, 8 warps (2m x 4n),
// warp 32x16, K-chunk 32, double-buffered. Grid 384.
// ---------------------------------------------------------------------------
__global__ __launch_bounds__(256, 3) void proj_mma(
    const float* __restrict__ Qin, const float* __restrict__ Kin,
    const float* __restrict__ Wq,  const float* __restrict__ Wk)
{
    __shared__ char smA[2][8192];   // 64 rows x 128B (hi32|lo32 bf16)
    __shared__ char smW[2][8192];   // 64 rows x 128B

    const int mtile = blockIdx.x >> 2;     // 0..95
    const int ntile = blockIdx.x & 3;
    const float* A; int isQ, m0;
    if (mtile < 32) { A = Qin; isQ = 1; m0 = mtile * 64; }
    else            { A = Kin; isQ = 0; m0 = (mtile - 32) * 64; }
    const float* W = isQ ? Wq : Wk;
    const int n0 = ntile * 64;

    const int tid  = threadIdx.x;
    const int wid  = tid >> 5;
    const int lane = tid & 31;
    const int wm = wid & 1;       // m sub (32 rows)
    const int wn = wid >> 1;      // n sub (16 cols)

    const int lrow = tid >> 3;        // 0..31
    const int fc   = tid & 7;         // float4 col (d0 = fc*4)
    const float* aBase = A + (size_t)(m0 + lrow) * DIMK + fc * 4;
    const float* wBase = W + (size_t)(n0 + lrow) * DIMK + fc * 4;
    const int r7L  = lrow & 7;
    const int hiOff = (((fc >> 1) ^ r7L) << 4) + (fc & 1) * 8;
    const int loOff = ((((fc >> 1) + 4) ^ r7L) << 4) + (fc & 1) * 8;

    const uint32_t smA_u = smem_u32(smA);
    const uint32_t smW_u = smem_u32(smW);

    float4 pa[2], pw[2];
#pragma unroll
    for (int p = 0; p < 2; p++) {
        pa[p] = *(const float4*)(aBase + p * 32 * DIMK);
        pw[p] = *(const float4*)(wBase + p * 32 * DIMK);
    }

#pragma unroll
    for (int p = 0; p < 2; p++) {
        uint32_t h0, l0, h1, l1;
        split2(pa[p].x, pa[p].y, h0, l0);
        split2(pa[p].z, pa[p].w, h1, l1);
        char* rb = smA[0] + (lrow + p * 32) * 128;
        *(uint2*)(rb + hiOff) = make_uint2(h0, h1);
        *(uint2*)(rb + loOff) = make_uint2(l0, l1);
        split2(pw[p].x, pw[p].y, h0, l0);
        split2(pw[p].z, pw[p].w, h1, l1);
        rb = smW[0] + (lrow + p * 32) * 128;
        *(uint2*)(rb + hiOff) = make_uint2(h0, h1);
        *(uint2*)(rb + loOff) = make_uint2(l0, l1);
    }
    __syncthreads();

    const int rowA0 = wm * 32 + (lane & 7) + ((lane >> 3) & 1) * 8;
    const int uaddA = (lane >> 4) & 1;
    const int rowB0 = wn * 16 + (lane & 7) + ((lane >> 4) & 1) * 8;
    const int uaddB = (lane >> 3) & 1;
    const int ar7 = rowA0 & 7;
    const int br7 = rowB0 & 7;

    float acc[2][2][4];
#pragma unroll
    for (int mm = 0; mm < 2; mm++)
#pragma unroll
        for (int nn = 0; nn < 2; nn++)
#pragma unroll
            for (int c = 0; c < 4; c++) acc[mm][nn][c] = 0.f;

    for (int ch = 0; ch < 32; ch++) {
        const int buf = ch & 1;
        if (ch < 31) {
            const int kc = (ch + 1) * 32;
#pragma unroll
            for (int p = 0; p < 2; p++) {
                pa[p] = *(const float4*)(aBase + p * 32 * DIMK + kc);
                pw[p] = *(const float4*)(wBase + p * 32 * DIMK + kc);
            }
        }

        const uint32_t aB = smA_u + buf * 8192;
        const uint32_t bB = smW_u + buf * 8192;
#pragma unroll
        for (int s = 0; s < 2; s++) {
            const int uHA = s * 2 + uaddA, uLA = uHA + 4;
            const int uHB = s * 2 + uaddB, uLB = uHB + 4;
            uint32_t aH0[4], aH1[4], aL0[4], aL1[4], bH[4], bL[4];
            LDSM4(aH0, aB + rowA0 * 128        + ((uHA ^ ar7) << 4));
            LDSM4(aH1, aB + (rowA0 + 16) * 128 + ((uHA ^ ar7) << 4));
            LDSM4(bH,  bB + rowB0 * 128        + ((uHB ^ br7) << 4));
            LDSM4(aL0, aB + rowA0 * 128        + ((uLA ^ ar7) << 4));
            LDSM4(aL1, aB + (rowA0 + 16) * 128 + ((uLA ^ ar7) << 4));
            LDSM4(bL,  bB + rowB0 * 128        + ((uLB ^ br7) << 4));

            MMA_BF16(acc[0][0], aH0, bH[0], bH[1]); MMA_BF16(acc[0][1], aH0, bH[2], bH[3]);
            MMA_BF16(acc[1][0], aH1, bH[0], bH[1]); MMA_BF16(acc[1][1], aH1, bH[2], bH[3]);
            MMA_BF16(acc[0][0], aH0, bL[0], bL[1]); MMA_BF16(acc[0][1], aH0, bL[2], bL[3]);
            MMA_BF16(acc[1][0], aH1, bL[0], bL[1]); MMA_BF16(acc[1][1], aH1, bL[2], bL[3]);
            MMA_BF16(acc[0][0], aL0, bH[0], bH[1]); MMA_BF16(acc[0][1], aL0, bH[2], bH[3]);
            MMA_BF16(acc[1][0], aL1, bH[0], bH[1]); MMA_BF16(acc[1][1], aL1, bH[2], bH[3]);
        }
        __syncthreads();

        if (ch < 31) {
            const int nb = 1 - buf;
#pragma unroll
            for (int p = 0; p < 2; p++) {
                uint32_t h0, l0, h1, l1;
                split2(pa[p].x, pa[p].y, h0, l0);
                split2(pa[p].z, pa[p].w, h1, l1);
                char* rb = smA[nb] + (lrow + p * 32) * 128;
                *(uint2*)(rb + hiOff) = make_uint2(h0, h1);
                *(uint2*)(rb + loOff) = make_uint2(l0, l1);
                split2(pw[p].x, pw[p].y, h0, l0);
                split2(pw[p].z, pw[p].w, h1, l1);
                rb = smW[nb] + (lrow + p * 32) * 128;
                *(uint2*)(rb + hiOff) = make_uint2(h0, h1);
                *(uint2*)(rb + loOff) = make_uint2(l0, l1);
            }
            __syncthreads();
        }
    }

    unsigned char* gbase = (unsigned char*)(isQ ? g_Q_sw : g_K_sw);
#pragma unroll
    for (int mm = 0; mm < 2; mm++) {
#pragma unroll
        for (int nn = 0; nn < 2; nn++) {
            const int n = n0 + wn * 16 + nn * 8 + (lane & 3) * 2;
            const int head = n >> 5;
            const int d0 = n & 31;
            const int u = d0 >> 3;
            const int within = (d0 & 7) * 2;
#pragma unroll
            for (int rr = 0; rr < 2; rr++) {
                const int m = m0 + wm * 32 + mm * 16 + (lane >> 2) + rr * 8;
                uint32_t hv, lv;
                split2(acc[mm][nn][rr * 2], acc[mm][nn][rr * 2 + 1], hv, lv);
                unsigned char* rb = gbase + (size_t)(m * 8 + head) * 128;
                const int r7 = m & 7;
                *(uint32_t*)(rb + ((u ^ r7) << 4) + within)       = hv;
                *(uint32_t*)(rb + (((u + 4) ^ r7) << 4) + within) = lv;
            }
        }
    }
}

// ---------------------------------------------------------------------------
// Main kernel: CTA 64k x 64q, 512 threads (16 warps, 4k x 4q), warp 16k x 16q.
// Same per-warp stream as R7; double the data reuse per staged byte.
// ---------------------------------------------------------------------------
#define SM_K    0          // 64 rows * 1KB = 65536
#define SM_Q    65536      // 64 rows * 1KB = 65536
#define SM_RPE  131072     // 257 * 16B = 4112
#define SM_QP   135184     // 64 * 4B
#define SM_KP   135440     // 64 * 4B
#define SM_TOT  135696

__global__ __launch_bounds__(512) void rpe_gate_mma(
    const int*   __restrict__ qpos, const int* __restrict__ kpos,
    const float* __restrict__ rpe_table,
    const float* __restrict__ w1, const float* __restrict__ b1,
    const float* __restrict__ w2, const float* __restrict__ b2,
    float* __restrict__ out)
{
    extern __shared__ char sm[];
    const uint32_t sb = smem_u32(sm);

    const int tid  = threadIdx.x;
    const int wid  = tid >> 5;
    const int lane = tid & 31;
    const int ktile = blockIdx.x;   // 64 k rows
    const int qtile = blockIdx.y;   // 64 q cols

    {
        const uint4* srcK = g_K_sw + (size_t)ktile * 4096;
        const uint4* srcQ = g_Q_sw + (size_t)qtile * 4096;
#pragma unroll
        for (int i = 0; i < 8; i++) {
            int u = tid + i * 512;
            asm volatile("cp.async.cg.shared.global [%0], [%1], 16;"
                :: "r"(sb + SM_K + u * 16), "l"(srcK + u) : "memory");
        }
#pragma unroll
        for (int i = 0; i < 8; i++) {
            int u = tid + i * 512;
            asm volatile("cp.async.cg.shared.global [%0], [%1], 16;"
                :: "r"(sb + SM_Q + u * 16), "l"(srcQ + u) : "memory");
        }
        asm volatile("cp.async.commit_group;");
    }
    for (int i = tid; i < 257; i += 512)
        *(float4*)(sm + SM_RPE + i * 16) = ((const float4*)rpe_table)[i];
    if (tid < 64) *(int*)(sm + SM_QP + tid * 4) = qpos[qtile * 64 + tid];
    if (tid >= 64 && tid < 128)
        *(int*)(sm + SM_KP + (tid - 64) * 4) = kpos[ktile * 64 + (tid - 64)];

    asm volatile("cp.async.wait_group 0;");
    __syncthreads();

    const int wk0 = (wid & 3) * 16;
    const int wq0 = (wid >> 2) * 16;

    const int rowA = wk0 + (lane & 7) + ((lane >> 3) & 1) * 8;
    const int uaddA = (lane >> 4) & 1;
    const int rowB = wq0 + (lane & 7) + ((lane >> 4) & 1) * 8;
    const int uaddB = (lane >> 3) & 1;
    const uint32_t aRow = sb + SM_K + rowA * 1024;
    const uint32_t bRow = sb + SM_Q + rowB * 1024;
    const int ar7 = rowA & 7;
    const int br7 = rowB & 7;

    float acc[8][2][4];
#pragma unroll
    for (int h = 0; h < 8; h++)
#pragma unroll
        for (int j = 0; j < 2; j++)
#pragma unroll
            for (int c = 0; c < 4; c++) acc[h][j][c] = 0.f;

#pragma unroll
    for (int h = 0; h < 8; h++) {
        const uint32_t ah = aRow + h * 128;
        const uint32_t bh = bRow + h * 128;
#pragma unroll
        for (int s = 0; s < 2; s++) {
            const int uHiA = s * 2 + uaddA, uLoA = uHiA + 4;
            const int uHiB = s * 2 + uaddB, uLoB = uHiB + 4;
            uint32_t aH[4], aL[4], bH[4], bL[4];
            LDSM4(aH, ah + ((uHiA ^ ar7) << 4));
            LDSM4(bH, bh + ((uHiB ^ br7) << 4));
            LDSM4(aL, ah + ((uLoA ^ ar7) << 4));
            LDSM4(bL, bh + ((uLoB ^ br7) << 4));
            MMA_BF16(acc[h][0], aH, bH[0], bH[1]);
            MMA_BF16(acc[h][1], aH, bH[2], bH[3]);
            MMA_BF16(acc[h][0], aH, bL[0], bL[1]);
            MMA_BF16(acc[h][1], aH, bL[2], bL[3]);
            MMA_BF16(acc[h][0], aL, bH[0], bH[1]);
            MMA_BF16(acc[h][1], aL, bH[2], bH[3]);
        }
    }

    float w1r[8][4], b1r[8], w2r[4][8], b2r[4];
#pragma unroll
    for (int e = 0; e < 8; e++) {
        b1r[e] = __ldg(&b1[e]);
#pragma unroll
        for (int h = 0; h < 4; h++) w1r[e][h] = __ldg(&w1[e * 4 + h]);
    }
#pragma unroll
    for (int h = 0; h < 4; h++) {
        b2r[h] = __ldg(&b2[h]);
#pragma unroll
        for (int e = 0; e < 8; e++) w2r[h][e] = __ldg(&w2[h * 8 + e]);
    }

    const float4* rpe_s = (const float4*)(sm + SM_RPE);
    const int* qp_s = (const int*)(sm + SM_QP);
    const int* kp_s = (const int*)(sm + SM_KP);

    const int krow0 = wk0 + (lane >> 2);
    const int qcol0 = wq0 + (lane & 3) * 2;
    const int kg0 = ktile * 64;
    const int qg0 = qtile * 64;

    int kv[2], qv[2][2];
#pragma unroll
    for (int kr = 0; kr < 2; kr++) kv[kr] = kp_s[krow0 + kr * 8];
#pragma unroll
    for (int j = 0; j < 2; j++)
#pragma unroll
        for (int qc = 0; qc < 2; qc++) qv[j][qc] = qp_s[qcol0 + j * 8 + qc];

#pragma unroll
    for (int j = 0; j < 2; j++) {
#pragma unroll
        for (int kr = 0; kr < 2; kr++) {
#pragma unroll
            for (int qc = 0; qc < 2; qc++) {
                const int c = kr * 2 + qc;
                int rel = qv[j][qc] - kv[kr];
                rel = rel < -128 ? -128 : (rel > 128 ? 128 : rel);
                float4 rp = rpe_s[rel + 128];
                float rph[4] = {rp.x, rp.y, rp.z, rp.w};

                float sh[4], gh[4];
#pragma unroll
                for (int h = 0; h < 4; h++) {
                    sh[h] = fmaxf(acc[h][j][c] + rph[h], 0.f);
                    gh[h] = acc[4 + h][j][c] + rph[h];
                }
                float zh[4] = {b2r[0], b2r[1], b2r[2], b2r[3]};
#pragma unroll
                for (int e = 0; e < 8; e++) {
                    float t = b1r[e];
#pragma unroll
                    for (int h = 0; h < 4; h++) t = fmaf(gh[h], w1r[e][h], t);
                    t = fmaxf(t, 0.f);
#pragma unroll
                    for (int h = 0; h < 4; h++) zh[h] = fmaf(t, w2r[h][e], zh[h]);
                }
                float o = 0.f;
#pragma unroll
                for (int h = 0; h < 4; h++) {
                    float g = __fdividef(1.f, 1.f + __expf(-zh[h]));
                    o = fmaf(sh[h], g, o);
                }
                const int qg = qg0 + qcol0 + j * 8 + qc;
                const int kg = kg0 + krow0 + kr * 8;
                out[(size_t)qg * NK + kg] = o;
            }
        }
    }
}

// ---------------------------------------------------------------------------
extern "C" void kernel_launch(void* const* d_in, const int* in_sizes, int n_in,
                              void* d_out, int out_size)
{
    const float* query = (const float*)d_in[0];
    const float* key   = (const float*)d_in[1];
    const int*   qpos  = (const int*)  d_in[2];
    const int*   kpos  = (const int*)  d_in[3];
    const float* Wq    = (const float*)d_in[4];
    const float* Wk    = (const float*)d_in[5];
    const float* rpe   = (const float*)d_in[6];
    const float* w1    = (const float*)d_in[7];
    const float* b1    = (const float*)d_in[8];
    const float* w2    = (const float*)d_in[9];
    const float* b2    = (const float*)d_in[10];
    float* out = (float*)d_out;
    (void)in_sizes; (void)n_in; (void)out_size;

    cudaFuncSetAttribute(rpe_gate_mma,
                         cudaFuncAttributeMaxDynamicSharedMemorySize, SM_TOT);

    proj_mma<<<384, 256>>>(query, key, Wq, Wk);
    rpe_gate_mma<<<dim3(NK / 64, NQ / 64), 512, SM_TOT>>>(
        qpos, kpos, rpe, w1, b1, w2, b2, out);
}

// round 13
// speedup vs baseline: 1.0950x; 1.0950x over previous
#include <cuda_runtime.h>
#include <cuda_bf16.h>
#include <cstdint>

#define NQ 2048
#define NK 4096
#define DIMK 1024

// Split-bf16 operand storage: per (pos, head) one 128B row = hi d0..31 | lo d0..31,
// 16B units permuted u ^= (pos & 7)  (conflict-free ldmatrix).
__device__ uint4 g_K_sw[NK * 8 * 8];   // (pos*8+head)*8 units
__device__ uint4 g_Q_sw[NQ * 8 * 8];

#define LDSM4(r, addr) \
    asm volatile("ldmatrix.sync.aligned.m8n8.x4.shared.b16 {%0,%1,%2,%3}, [%4];" \
        : "=r"((r)[0]),"=r"((r)[1]),"=r"((r)[2]),"=r"((r)[3]) : "r"(addr))

#define MMA_BF16(accp, a, b0, b1) \
    asm volatile("mma.sync.aligned.m16n8k16.row.col.f32.bf16.bf16.f32 " \
        "{%0,%1,%2,%3}, {%4,%5,%6,%7}, {%8,%9}, {%0,%1,%2,%3};" \
        : "+f"((accp)[0]),"+f"((accp)[1]),"+f"((accp)[2]),"+f"((accp)[3]) \
        : "r"((a)[0]),"r"((a)[1]),"r"((a)[2]),"r"((a)[3]), "r"(b0),"r"(b1))

static __device__ __forceinline__ uint32_t smem_u32(const void* p) {
    uint32_t a;
    asm("{ .reg .u64 t; cvta.to.shared.u64 t, %1; cvt.u32.u64 %0, t; }"
        : "=r"(a) : "l"(p));
    return a;
}

static __device__ __forceinline__ void split2(float f0, float f1,
                                              uint32_t& hv, uint32_t& lv) {
    __nv_bfloat16 h0 = __float2bfloat16(f0);
    __nv_bfloat16 h1 = __float2bfloat16(f1);
    __nv_bfloat16 l0 = __float2bfloat16(f0 - __bfloat162float(h0));
    __nv_bfloat16 l1 = __float2bfloat16(f1 - __bfloat162float(h1));
    hv = (uint32_t)__bfloat16_as_ushort(h0) | ((uint32_t)__bfloat16_as_ushort(h1) << 16);
    lv = (uint32_t)__bfloat16_as_ushort(l0) | ((uint32_t)__bfloat16_as_ushort(l1) << 16);
}

// ---------------------------------------------------------------------------
// Tensor-core projection: CTA 64M x 64N, 8 warps (2m x 4n), warp 32x16,
// K-chunk 32, double-buffered. Grid 384.
// Epilogue: fragments scatter into an smem stage (swizzle baked in), then
// 128B-coalesced uint4 stores to gmem. STAGE_PITCH = 144 (16B-aligned).
// ---------------------------------------------------------------------------
#define STAGE_PITCH 144   // 16-byte aligned (uint4 drain), bank-rotating

__global__ __launch_bounds__(256, 3) void proj_mma(
    const float* __restrict__ Qin, const float* __restrict__ Kin,
    const float* __restrict__ Wq,  const float* __restrict__ Wk)
{
    __shared__ char smem_all[32768];
    // [0, 16384)       : A double buffer (2 x 8192)
    // [16384, 32768)   : W double buffer (2 x 8192)
    // after mainloop   : reused as 128-row x 144B stage (18432 B)

    const int mtile = blockIdx.x >> 2;     // 0..95
    const int ntile = blockIdx.x & 3;
    const float* A; int isQ, m0;
    if (mtile < 32) { A = Qin; isQ = 1; m0 = mtile * 64; }
    else            { A = Kin; isQ = 0; m0 = (mtile - 32) * 64; }
    const float* W = isQ ? Wq : Wk;
    const int n0 = ntile * 64;

    const int tid  = threadIdx.x;
    const int wid  = tid >> 5;
    const int lane = tid & 31;
    const int wm = wid & 1;       // m sub (32 rows)
    const int wn = wid >> 1;      // n sub (16 cols)

    const int lrow = tid >> 3;        // 0..31
    const int fc   = tid & 7;         // float4 col (d0 = fc*4)
    const float* aBase = A + (size_t)(m0 + lrow) * DIMK + fc * 4;
    const float* wBase = W + (size_t)(n0 + lrow) * DIMK + fc * 4;
    const int r7L  = lrow & 7;
    const int hiOff = (((fc >> 1) ^ r7L) << 4) + (fc & 1) * 8;
    const int loOff = ((((fc >> 1) + 4) ^ r7L) << 4) + (fc & 1) * 8;

    const uint32_t sm_u = smem_u32(smem_all);

    float4 pa[2], pw[2];
#pragma unroll
    for (int p = 0; p < 2; p++) {
        pa[p] = *(const float4*)(aBase + p * 32 * DIMK);
        pw[p] = *(const float4*)(wBase + p * 32 * DIMK);
    }

#pragma unroll
    for (int p = 0; p < 2; p++) {
        uint32_t h0, l0, h1, l1;
        split2(pa[p].x, pa[p].y, h0, l0);
        split2(pa[p].z, pa[p].w, h1, l1);
        char* rb = smem_all + (lrow + p * 32) * 128;
        *(uint2*)(rb + hiOff) = make_uint2(h0, h1);
        *(uint2*)(rb + loOff) = make_uint2(l0, l1);
        split2(pw[p].x, pw[p].y, h0, l0);
        split2(pw[p].z, pw[p].w, h1, l1);
        rb = smem_all + 16384 + (lrow + p * 32) * 128;
        *(uint2*)(rb + hiOff) = make_uint2(h0, h1);
        *(uint2*)(rb + loOff) = make_uint2(l0, l1);
    }
    __syncthreads();

    const int rowA0 = wm * 32 + (lane & 7) + ((lane >> 3) & 1) * 8;
    const int uaddA = (lane >> 4) & 1;
    const int rowB0 = wn * 16 + (lane & 7) + ((lane >> 4) & 1) * 8;
    const int uaddB = (lane >> 3) & 1;
    const int ar7 = rowA0 & 7;
    const int br7 = rowB0 & 7;

    float acc[2][2][4];
#pragma unroll
    for (int mm = 0; mm < 2; mm++)
#pragma unroll
        for (int nn = 0; nn < 2; nn++)
#pragma unroll
            for (int c = 0; c < 4; c++) acc[mm][nn][c] = 0.f;

    for (int ch = 0; ch < 32; ch++) {
        const int buf = ch & 1;
        if (ch < 31) {
            const int kc = (ch + 1) * 32;
#pragma unroll
            for (int p = 0; p < 2; p++) {
                pa[p] = *(const float4*)(aBase + p * 32 * DIMK + kc);
                pw[p] = *(const float4*)(wBase + p * 32 * DIMK + kc);
            }
        }

        const uint32_t aB = sm_u + buf * 8192;
        const uint32_t bB = sm_u + 16384 + buf * 8192;
#pragma unroll
        for (int s = 0; s < 2; s++) {
            const int uHA = s * 2 + uaddA, uLA = uHA + 4;
            const int uHB = s * 2 + uaddB, uLB = uHB + 4;
            uint32_t aH0[4], aH1[4], aL0[4], aL1[4], bH[4], bL[4];
            LDSM4(aH0, aB + rowA0 * 128        + ((uHA ^ ar7) << 4));
            LDSM4(aH1, aB + (rowA0 + 16) * 128 + ((uHA ^ ar7) << 4));
            LDSM4(bH,  bB + rowB0 * 128        + ((uHB ^ br7) << 4));
            LDSM4(aL0, aB + rowA0 * 128        + ((uLA ^ ar7) << 4));
            LDSM4(aL1, aB + (rowA0 + 16) * 128 + ((uLA ^ ar7) << 4));
            LDSM4(bL,  bB + rowB0 * 128        + ((uLB ^ br7) << 4));

            MMA_BF16(acc[0][0], aH0, bH[0], bH[1]); MMA_BF16(acc[0][1], aH0, bH[2], bH[3]);
            MMA_BF16(acc[1][0], aH1, bH[0], bH[1]); MMA_BF16(acc[1][1], aH1, bH[2], bH[3]);
            MMA_BF16(acc[0][0], aH0, bL[0], bL[1]); MMA_BF16(acc[0][1], aH0, bL[2], bL[3]);
            MMA_BF16(acc[1][0], aH1, bL[0], bL[1]); MMA_BF16(acc[1][1], aH1, bL[2], bL[3]);
            MMA_BF16(acc[0][0], aL0, bH[0], bH[1]); MMA_BF16(acc[0][1], aL0, bH[2], bH[3]);
            MMA_BF16(acc[1][0], aL1, bH[0], bH[1]); MMA_BF16(acc[1][1], aL1, bH[2], bH[3]);
        }
        __syncthreads();

        if (ch < 31) {
            const int nb = 1 - buf;
#pragma unroll
            for (int p = 0; p < 2; p++) {
                uint32_t h0, l0, h1, l1;
                split2(pa[p].x, pa[p].y, h0, l0);
                split2(pa[p].z, pa[p].w, h1, l1);
                char* rb = smem_all + nb * 8192 + (lrow + p * 32) * 128;
                *(uint2*)(rb + hiOff) = make_uint2(h0, h1);
                *(uint2*)(rb + loOff) = make_uint2(l0, l1);
                split2(pw[p].x, pw[p].y, h0, l0);
                split2(pw[p].z, pw[p].w, h1, l1);
                rb = smem_all + 16384 + nb * 8192 + (lrow + p * 32) * 128;
                *(uint2*)(rb + hiOff) = make_uint2(h0, h1);
                *(uint2*)(rb + loOff) = make_uint2(l0, l1);
            }
            __syncthreads();
        }
    }
    // After final unconditional __syncthreads(): smem free for staging.

    // ---- Stage fragments into smem rows (swizzle baked in) ----
    // Stage row = head_local*64 + local_m, pitch 144B.
#pragma unroll
    for (int mm = 0; mm < 2; mm++) {
#pragma unroll
        for (int nn = 0; nn < 2; nn++) {
            const int local_n = wn * 16 + nn * 8 + (lane & 3) * 2;
            const int head_local = local_n >> 5;
            const int d0 = local_n & 31;
            const int u = d0 >> 3;
            const int within = (d0 & 7) * 2;
#pragma unroll
            for (int rr = 0; rr < 2; rr++) {
                const int local_m = wm * 32 + mm * 16 + (lane >> 2) + rr * 8;
                uint32_t hv, lv;
                split2(acc[mm][nn][rr * 2], acc[mm][nn][rr * 2 + 1], hv, lv);
                char* rb = smem_all + (head_local * 64 + local_m) * STAGE_PITCH;
                const int r7 = local_m & 7;
                *(uint32_t*)(rb + ((u ^ r7) << 4) + within)       = hv;
                *(uint32_t*)(rb + (((u + 4) ^ r7) << 4) + within) = lv;
            }
        }
    }
    __syncthreads();

    // ---- Coalesced gmem write: 128 rows x 128B, uint4 per thread, 4 passes ----
    unsigned char* gbase = (unsigned char*)(isQ ? g_Q_sw : g_K_sw);
#pragma unroll
    for (int pass = 0; pass < 4; pass++) {
        const int row = (tid >> 3) + pass * 32;     // 0..127
        const int unit = tid & 7;
        const int head_local = row >> 6;
        const int local_m = row & 63;
        const int m = m0 + local_m;
        const int head = (n0 >> 5) + head_local;
        uint4 v = *(uint4*)(smem_all + row * STAGE_PITCH + unit * 16);
        *(uint4*)(gbase + (size_t)(m * 8 + head) * 128 + unit * 16) = v;
    }
}

// ---------------------------------------------------------------------------
// Main kernel (exact R7/R10 config, 97.3us measured): CTA 64k x 32q, 8 warps.
// ---------------------------------------------------------------------------
#define SM_K    0
#define SM_Q    65536
#define SM_RPE  98304
#define SM_QP   102416
#define SM_KP   102544
#define SM_TOT  102800

__global__ __launch_bounds__(256) void rpe_gate_mma(
    const int*   __restrict__ qpos, const int* __restrict__ kpos,
    const float* __restrict__ rpe_table,
    const float* __restrict__ w1, const float* __restrict__ b1,
    const float* __restrict__ w2, const float* __restrict__ b2,
    float* __restrict__ out)
{
    extern __shared__ char sm[];
    const uint32_t sb = smem_u32(sm);

    const int tid  = threadIdx.x;
    const int wid  = tid >> 5;
    const int lane = tid & 31;
    const int ktile = blockIdx.x;
    const int qtile = blockIdx.y;

    {
        const uint4* srcK = g_K_sw + (size_t)ktile * 4096;
        const uint4* srcQ = g_Q_sw + (size_t)qtile * 2048;
#pragma unroll
        for (int i = 0; i < 16; i++) {
            int u = tid + i * 256;
            asm volatile("cp.async.cg.shared.global [%0], [%1], 16;"
                :: "r"(sb + SM_K + u * 16), "l"(srcK + u) : "memory");
        }
#pragma unroll
        for (int i = 0; i < 8; i++) {
            int u = tid + i * 256;
            asm volatile("cp.async.cg.shared.global [%0], [%1], 16;"
                :: "r"(sb + SM_Q + u * 16), "l"(srcQ + u) : "memory");
        }
        asm volatile("cp.async.commit_group;");
    }
    for (int i = tid; i < 257; i += 256)
        *(float4*)(sm + SM_RPE + i * 16) = ((const float4*)rpe_table)[i];
    if (tid < 32) *(int*)(sm + SM_QP + tid * 4) = qpos[qtile * 32 + tid];
    if (tid < 64) *(int*)(sm + SM_KP + tid * 4) = kpos[ktile * 64 + tid];

    asm volatile("cp.async.wait_group 0;");
    __syncthreads();

    const int wk0 = (wid & 3) * 16;
    const int wq0 = (wid >> 2) * 16;

    const int rowA = wk0 + (lane & 7) + ((lane >> 3) & 1) * 8;
    const int uaddA = (lane >> 4) & 1;
    const int rowB = wq0 + (lane & 7) + ((lane >> 4) & 1) * 8;
    const int uaddB = (lane >> 3) & 1;
    const uint32_t aRow = sb + SM_K + rowA * 1024;
    const uint32_t bRow = sb + SM_Q + rowB * 1024;
    const int ar7 = rowA & 7;
    const int br7 = rowB & 7;

    float acc[8][2][4];
#pragma unroll
    for (int h = 0; h < 8; h++)
#pragma unroll
        for (int j = 0; j < 2; j++)
#pragma unroll
            for (int c = 0; c < 4; c++) acc[h][j][c] = 0.f;

#pragma unroll
    for (int h = 0; h < 8; h++) {
        const uint32_t ah = aRow + h * 128;
        const uint32_t bh = bRow + h * 128;
#pragma unroll
        for (int s = 0; s < 2; s++) {
            const int uHiA = s * 2 + uaddA, uLoA = uHiA + 4;
            const int uHiB = s * 2 + uaddB, uLoB = uHiB + 4;
            uint32_t aH[4], aL[4], bH[4], bL[4];
            LDSM4(aH, ah + ((uHiA ^ ar7) << 4));
            LDSM4(bH, bh + ((uHiB ^ br7) << 4));
            LDSM4(aL, ah + ((uLoA ^ ar7) << 4));
            LDSM4(bL, bh + ((uLoB ^ br7) << 4));
            MMA_BF16(acc[h][0], aH, bH[0], bH[1]);
            MMA_BF16(acc[h][1], aH, bH[2], bH[3]);
            MMA_BF16(acc[h][0], aH, bL[0], bL[1]);
            MMA_BF16(acc[h][1], aH, bL[2], bL[3]);
            MMA_BF16(acc[h][0], aL, bH[0], bH[1]);
            MMA_BF16(acc[h][1], aL, bH[2], bH[3]);
        }
    }

    float w1r[8][4], b1r[8], w2r[4][8], b2r[4];
#pragma unroll
    for (int e = 0; e < 8; e++) {
        b1r[e] = __ldg(&b1[e]);
#pragma unroll
        for (int h = 0; h < 4; h++) w1r[e][h] = __ldg(&w1[e * 4 + h]);
    }
#pragma unroll
    for (int h = 0; h < 4; h++) {
        b2r[h] = __ldg(&b2[h]);
#pragma unroll
        for (int e = 0; e < 8; e++) w2r[h][e] = __ldg(&w2[h * 8 + e]);
    }

    const float4* rpe_s = (const float4*)(sm + SM_RPE);
    const int* qp_s = (const int*)(sm + SM_QP);
    const int* kp_s = (const int*)(sm + SM_KP);

    const int krow0 = wk0 + (lane >> 2);
    const int qcol0 = wq0 + (lane & 3) * 2;
    const int kg0 = ktile * 64;
    const int qg0 = qtile * 32;

    int kv[2], qv[2][2];
#pragma unroll
    for (int kr = 0; kr < 2; kr++) kv[kr] = kp_s[krow0 + kr * 8];
#pragma unroll
    for (int j = 0; j < 2; j++)
#pragma unroll
        for (int qc = 0; qc < 2; qc++) qv[j][qc] = qp_s[qcol0 + j * 8 + qc];

#pragma unroll
    for (int j = 0; j < 2; j++) {
#pragma unroll
        for (int kr = 0; kr < 2; kr++) {
#pragma unroll
            for (int qc = 0; qc < 2; qc++) {
                const int c = kr * 2 + qc;
                int rel = qv[j][qc] - kv[kr];
                rel = rel < -128 ? -128 : (rel > 128 ? 128 : rel);
                float4 rp = rpe_s[rel + 128];
                float rph[4] = {rp.x, rp.y, rp.z, rp.w};

                float sh[4], gh[4];
#pragma unroll
                for (int h = 0; h < 4; h++) {
                    sh[h] = fmaxf(acc[h][j][c] + rph[h], 0.f);
                    gh[h] = acc[4 + h][j][c] + rph[h];
                }
                float zh[4] = {b2r[0], b2r[1], b2r[2], b2r[3]};
#pragma unroll
                for (int e = 0; e < 8; e++) {
                    float t = b1r[e];
#pragma unroll
                    for (int h = 0; h < 4; h++) t = fmaf(gh[h], w1r[e][h], t);
                    t = fmaxf(t, 0.f);
#pragma unroll
                    for (int h = 0; h < 4; h++) zh[h] = fmaf(t, w2r[h][e], zh[h]);
                }
                float o = 0.f;
#pragma unroll
                for (int h = 0; h < 4; h++) {
                    float g = __fdividef(1.f, 1.f + __expf(-zh[h]));
                    o = fmaf(sh[h], g, o);
                }
                const int qg = qg0 + qcol0 + j * 8 + qc;
                const int kg = kg0 + krow0 + kr * 8;
                out[(size_t)qg * NK + kg] = o;
            }
        }
    }
}

// ---------------------------------------------------------------------------
extern "C" void kernel_launch(void* const* d_in, const int* in_sizes, int n_in,
                              void* d_out, int out_size)
{
    const float* query = (const float*)d_in[0];
    const float* key   = (const float*)d_in[1];
    const int*   qpos  = (const int*)  d_in[2];
    const int*   kpos  = (const int*)  d_in[3];
    const float* Wq    = (const float*)d_in[4];
    const float* Wk    = (const float*)d_in[5];
    const float* rpe   = (const float*)d_in[6];
    const float* w1    = (const float*)d_in[7];
    const float* b1    = (const float*)d_in[8];
    const float* w2    = (const float*)d_in[9];
    const float* b2    = (const float*)d_in[10];
    float* out = (float*)d_out;
    (void)in_sizes; (void)n_in; (void)out_size;

    cudaFuncSetAttribute(rpe_gate_mma,
                         cudaFuncAttributeMaxDynamicSharedMemorySize, SM_TOT);

    proj_mma<<<384, 256>>>(query, key, Wq, Wk);
    rpe_gate_mma<<<dim3(NK / 64, NQ / 32), 256, SM_TOT>>>(
        qpos, kpos, rpe, w1, b1, w2, b2, out);
}

// round 14
// speedup vs baseline: 1.1614x; 1.0606x over previous
#include <cuda_runtime.h>
#include <cuda_bf16.h>
#include <cstdint>

#define NQ 2048
#define NK 4096
#define DIMK 1024

// Split-bf16 operand tiles for the main kernel: per (pos, head) one 128B row =
// hi d0..31 | lo d0..31, 16B units permuted u ^= (pos & 7).
__device__ uint4 g_K_sw[NK * 8 * 8];   // (pos*8+head)*8 units
__device__ uint4 g_Q_sw[NQ * 8 * 8];

// Pre-converted projection operands, chunked layout: [chunk 0..31][row][128B row]
// Row content: hi bf16 of k-chunk d0..31 | lo bf16, 16B units XORed by (row&7).
// g_AC rows: 0..2047 = query, 2048..6143 = key.   g_WC rows: 0..255 = Wq, 256..511 = Wk.
__device__ uint4 g_AC[32 * 6144 * 8];   // 25.2 MB
__device__ uint4 g_WC[32 * 512 * 8];    // 2 MB

#define LDSM4(r, addr) \
    asm volatile("ldmatrix.sync.aligned.m8n8.x4.shared.b16 {%0,%1,%2,%3}, [%4];" \
        : "=r"((r)[0]),"=r"((r)[1]),"=r"((r)[2]),"=r"((r)[3]) : "r"(addr))

#define MMA_BF16(accp, a, b0, b1) \
    asm volatile("mma.sync.aligned.m16n8k16.row.col.f32.bf16.bf16.f32 " \
        "{%0,%1,%2,%3}, {%4,%5,%6,%7}, {%8,%9}, {%0,%1,%2,%3};" \
        : "+f"((accp)[0]),"+f"((accp)[1]),"+f"((accp)[2]),"+f"((accp)[3]) \
        : "r"((a)[0]),"r"((a)[1]),"r"((a)[2]),"r"((a)[3]), "r"(b0),"r"(b1))

static __device__ __forceinline__ uint32_t smem_u32(const void* p) {
    uint32_t a;
    asm("{ .reg .u64 t; cvta.to.shared.u64 t, %1; cvt.u32.u64 %0, t; }"
        : "=r"(a) : "l"(p));
    return a;
}

static __device__ __forceinline__ void split2(float f0, float f1,
                                              uint32_t& hv, uint32_t& lv) {
    __nv_bfloat16 h0 = __float2bfloat16(f0);
    __nv_bfloat16 h1 = __float2bfloat16(f1);
    __nv_bfloat16 l0 = __float2bfloat16(f0 - __bfloat162float(h0));
    __nv_bfloat16 l1 = __float2bfloat16(f1 - __bfloat162float(h1));
    hv = (uint32_t)__bfloat16_as_ushort(h0) | ((uint32_t)__bfloat16_as_ushort(h1) << 16);
    lv = (uint32_t)__bfloat16_as_ushort(l0) | ((uint32_t)__bfloat16_as_ushort(l1) << 16);
}

// ---------------------------------------------------------------------------
// Convert kernel: fp32 inputs -> bf16 hi|lo split, chunked swizzled layout.
// One thread = 8 consecutive fp32 of one (row, chunk) -> one 16B hi + 16B lo.
// Grid: 6656 rows * 128 work-items / 256 = 3328 blocks.
// ---------------------------------------------------------------------------
__global__ __launch_bounds__(256) void convert_split(
    const float* __restrict__ Qin, const float* __restrict__ Kin,
    const float* __restrict__ Wq,  const float* __restrict__ Wk)
{
    const int t = blockIdx.x * 256 + threadIdx.x;   // 0 .. 851967
    const int r = t >> 7;                            // global row 0..6655
    const int rem = t & 127;
    const int ch = rem >> 2;                         // k-chunk 0..31
    const int g  = rem & 3;                          // 8-elem group within chunk

    const float* src;
    unsigned char* dstbase;
    int rows, lr;
    if (r < 6144) {
        lr = r;
        src = (r < 2048) ? (Qin + (size_t)r * DIMK)
                         : (Kin + (size_t)(r - 2048) * DIMK);
        dstbase = (unsigned char*)g_AC; rows = 6144;
    } else {
        lr = r - 6144;                               // 0..511
        src = (lr < 256) ? (Wq + (size_t)lr * DIMK)
                         : (Wk + (size_t)(lr - 256) * DIMK);
        dstbase = (unsigned char*)g_WC; rows = 512;
    }

    const float* p = src + ch * 32 + g * 8;
    float4 v0 = *(const float4*)p;
    float4 v1 = *(const float4*)(p + 4);

    uint32_t h[4], l[4];
    split2(v0.x, v0.y, h[0], l[0]);
    split2(v0.z, v0.w, h[1], l[1]);
    split2(v1.x, v1.y, h[2], l[2]);
    split2(v1.z, v1.w, h[3], l[3]);

    const int r7 = lr & 7;
    unsigned char* rowb = dstbase + ((size_t)ch * rows + lr) * 128;
    *(uint4*)(rowb + ((g ^ r7) << 4))       = make_uint4(h[0], h[1], h[2], h[3]);
    *(uint4*)(rowb + (((g + 4) ^ r7) << 4)) = make_uint4(l[0], l[1], l[2], l[3]);
}

// ---------------------------------------------------------------------------
// Projection: pure-consumer tcgen-less GEMM. CTA 64M x 64N, 8 warps (2m x 4n),
// warp 32x16, K-chunk 32, cp.async 4-stage pipeline (64KB smem), 1 barrier
// per chunk. Epilogue: smem-staged coalesced store (R13). Grid 384.
// ---------------------------------------------------------------------------
#define PSTAGE 16384       // per stage: 8KB A rows + 8KB W rows
#define PROJ_SMEM 65536
#define STAGE_PITCH 144    // 16B-aligned drain pitch

__global__ __launch_bounds__(256, 3) void proj_mma()
{
    extern __shared__ char smem_all[];

    const int mtile = blockIdx.x >> 2;     // 0..95
    const int ntile = blockIdx.x & 3;
    int isQ, m0, m0row;
    if (mtile < 32) { isQ = 1; m0 = mtile * 64;        m0row = m0; }
    else            { isQ = 0; m0 = (mtile - 32) * 64; m0row = 2048 + m0; }
    const int n0 = ntile * 64;
    const int wrow = (isQ ? 0 : 256) + n0;

    const int tid  = threadIdx.x;
    const int wid  = tid >> 5;
    const int lane = tid & 31;
    const int wm = wid & 1;
    const int wn = wid >> 1;

    const uint32_t sm_u = smem_u32(smem_all);

    // stage fill: 8KB A (512 uint4) + 8KB W, 2+2 cp.async per thread
#define PROJ_ISSUE(ch)  do {                                                   \
        const uint32_t st_ = sm_u + ((ch) & 3) * PSTAGE;                       \
        const uint4* sA_ = g_AC + ((size_t)(ch) * 6144 + m0row) * 8;           \
        const uint4* sW_ = g_WC + ((size_t)(ch) * 512  + wrow) * 8;            \
        asm volatile("cp.async.cg.shared.global [%0], [%1], 16;"               \
            :: "r"(st_ + tid * 16),          "l"(sA_ + tid)       : "memory"); \
        asm volatile("cp.async.cg.shared.global [%0], [%1], 16;"               \
            :: "r"(st_ + (tid + 256) * 16),  "l"(sA_ + tid + 256) : "memory"); \
        asm volatile("cp.async.cg.shared.global [%0], [%1], 16;"               \
            :: "r"(st_ + 8192 + tid * 16),         "l"(sW_ + tid) : "memory"); \
        asm volatile("cp.async.cg.shared.global [%0], [%1], 16;"               \
            :: "r"(st_ + 8192 + (tid + 256) * 16), "l"(sW_ + tid + 256) : "memory"); \
    } while (0)

    PROJ_ISSUE(0); asm volatile("cp.async.commit_group;");
    PROJ_ISSUE(1); asm volatile("cp.async.commit_group;");
    PROJ_ISSUE(2); asm volatile("cp.async.commit_group;");

    const int rowA0 = wm * 32 + (lane & 7) + ((lane >> 3) & 1) * 8;
    const int uaddA = (lane >> 4) & 1;
    const int rowB0 = wn * 16 + (lane & 7) + ((lane >> 4) & 1) * 8;
    const int uaddB = (lane >> 3) & 1;
    const int ar7 = rowA0 & 7;
    const int br7 = rowB0 & 7;

    float acc[2][2][4];
#pragma unroll
    for (int mm = 0; mm < 2; mm++)
#pragma unroll
        for (int nn = 0; nn < 2; nn++)
#pragma unroll
            for (int c = 0; c < 4; c++) acc[mm][nn][c] = 0.f;

    for (int ch = 0; ch < 32; ch++) {
        asm volatile("cp.async.wait_group 2;");
        __syncthreads();
        if (ch + 3 < 32) { PROJ_ISSUE(ch + 3); }
        asm volatile("cp.async.commit_group;");   // empty group at tail keeps count uniform

        const uint32_t aB = sm_u + (ch & 3) * PSTAGE;
        const uint32_t bB = aB + 8192;
#pragma unroll
        for (int s = 0; s < 2; s++) {
            const int uHA = s * 2 + uaddA, uLA = uHA + 4;
            const int uHB = s * 2 + uaddB, uLB = uHB + 4;
            uint32_t aH0[4], aH1[4], aL0[4], aL1[4], bH[4], bL[4];
            LDSM4(aH0, aB + rowA0 * 128        + ((uHA ^ ar7) << 4));
            LDSM4(aH1, aB + (rowA0 + 16) * 128 + ((uHA ^ ar7) << 4));
            LDSM4(bH,  bB + rowB0 * 128        + ((uHB ^ br7) << 4));
            LDSM4(aL0, aB + rowA0 * 128        + ((uLA ^ ar7) << 4));
            LDSM4(aL1, aB + (rowA0 + 16) * 128 + ((uLA ^ ar7) << 4));
            LDSM4(bL,  bB + rowB0 * 128        + ((uLB ^ br7) << 4));

            MMA_BF16(acc[0][0], aH0, bH[0], bH[1]); MMA_BF16(acc[0][1], aH0, bH[2], bH[3]);
            MMA_BF16(acc[1][0], aH1, bH[0], bH[1]); MMA_BF16(acc[1][1], aH1, bH[2], bH[3]);
            MMA_BF16(acc[0][0], aH0, bL[0], bL[1]); MMA_BF16(acc[0][1], aH0, bL[2], bL[3]);
            MMA_BF16(acc[1][0], aH1, bL[0], bL[1]); MMA_BF16(acc[1][1], aH1, bL[2], bL[3]);
            MMA_BF16(acc[0][0], aL0, bH[0], bH[1]); MMA_BF16(acc[0][1], aL0, bH[2], bH[3]);
            MMA_BF16(acc[1][0], aL1, bH[0], bH[1]); MMA_BF16(acc[1][1], aL1, bH[2], bH[3]);
        }
    }
    asm volatile("cp.async.wait_group 0;");
    __syncthreads();

    // ---- Stage fragments into smem rows (swizzle baked in), pitch 144B ----
#pragma unroll
    for (int mm = 0; mm < 2; mm++) {
#pragma unroll
        for (int nn = 0; nn < 2; nn++) {
            const int local_n = wn * 16 + nn * 8 + (lane & 3) * 2;
            const int head_local = local_n >> 5;
            const int d0 = local_n & 31;
            const int u = d0 >> 3;
            const int within = (d0 & 7) * 2;
#pragma unroll
            for (int rr = 0; rr < 2; rr++) {
                const int local_m = wm * 32 + mm * 16 + (lane >> 2) + rr * 8;
                uint32_t hv, lv;
                split2(acc[mm][nn][rr * 2], acc[mm][nn][rr * 2 + 1], hv, lv);
                char* rb = smem_all + (head_local * 64 + local_m) * STAGE_PITCH;
                const int r7 = local_m & 7;
                *(uint32_t*)(rb + ((u ^ r7) << 4) + within)       = hv;
                *(uint32_t*)(rb + (((u + 4) ^ r7) << 4) + within) = lv;
            }
        }
    }
    __syncthreads();

    // ---- Coalesced gmem write: 128 rows x 128B ----
    unsigned char* gbase = (unsigned char*)(isQ ? g_Q_sw : g_K_sw);
#pragma unroll
    for (int pass = 0; pass < 4; pass++) {
        const int row = (tid >> 3) + pass * 32;
        const int unit = tid & 7;
        const int head_local = row >> 6;
        const int local_m = row & 63;
        const int m = m0 + local_m;
        const int head = (n0 >> 5) + head_local;
        uint4 v = *(uint4*)(smem_all + row * STAGE_PITCH + unit * 16);
        *(uint4*)(gbase + (size_t)(m * 8 + head) * 128 + unit * 16) = v;
    }
}

// ---------------------------------------------------------------------------
// Main kernel (exact R7/R10 config, 97.8us measured): CTA 64k x 32q, 8 warps.
// ---------------------------------------------------------------------------
#define SM_K    0
#define SM_Q    65536
#define SM_RPE  98304
#define SM_QP   102416
#define SM_KP   102544
#define SM_TOT  102800

__global__ __launch_bounds__(256) void rpe_gate_mma(
    const int*   __restrict__ qpos, const int* __restrict__ kpos,
    const float* __restrict__ rpe_table,
    const float* __restrict__ w1, const float* __restrict__ b1,
    const float* __restrict__ w2, const float* __restrict__ b2,
    float* __restrict__ out)
{
    extern __shared__ char sm[];
    const uint32_t sb = smem_u32(sm);

    const int tid  = threadIdx.x;
    const int wid  = tid >> 5;
    const int lane = tid & 31;
    const int ktile = blockIdx.x;
    const int qtile = blockIdx.y;

    {
        const uint4* srcK = g_K_sw + (size_t)ktile * 4096;
        const uint4* srcQ = g_Q_sw + (size_t)qtile * 2048;
#pragma unroll
        for (int i = 0; i < 16; i++) {
            int u = tid + i * 256;
            asm volatile("cp.async.cg.shared.global [%0], [%1], 16;"
                :: "r"(sb + SM_K + u * 16), "l"(srcK + u) : "memory");
        }
#pragma unroll
        for (int i = 0; i < 8; i++) {
            int u = tid + i * 256;
            asm volatile("cp.async.cg.shared.global [%0], [%1], 16;"
                :: "r"(sb + SM_Q + u * 16), "l"(srcQ + u) : "memory");
        }
        asm volatile("cp.async.commit_group;");
    }
    for (int i = tid; i < 257; i += 256)
        *(float4*)(sm + SM_RPE + i * 16) = ((const float4*)rpe_table)[i];
    if (tid < 32) *(int*)(sm + SM_QP + tid * 4) = qpos[qtile * 32 + tid];
    if (tid < 64) *(int*)(sm + SM_KP + tid * 4) = kpos[ktile * 64 + tid];

    asm volatile("cp.async.wait_group 0;");
    __syncthreads();

    const int wk0 = (wid & 3) * 16;
    const int wq0 = (wid >> 2) * 16;

    const int rowA = wk0 + (lane & 7) + ((lane >> 3) & 1) * 8;
    const int uaddA = (lane >> 4) & 1;
    const int rowB = wq0 + (lane & 7) + ((lane >> 4) & 1) * 8;
    const int uaddB = (lane >> 3) & 1;
    const uint32_t aRow = sb + SM_K + rowA * 1024;
    const uint32_t bRow = sb + SM_Q + rowB * 1024;
    const int ar7 = rowA & 7;
    const int br7 = rowB & 7;

    float acc[8][2][4];
#pragma unroll
    for (int h = 0; h < 8; h++)
#pragma unroll
        for (int j = 0; j < 2; j++)
#pragma unroll
            for (int c = 0; c < 4; c++) acc[h][j][c] = 0.f;

#pragma unroll
    for (int h = 0; h < 8; h++) {
        const uint32_t ah = aRow + h * 128;
        const uint32_t bh = bRow + h * 128;
#pragma unroll
        for (int s = 0; s < 2; s++) {
            const int uHiA = s * 2 + uaddA, uLoA = uHiA + 4;
            const int uHiB = s * 2 + uaddB, uLoB = uHiB + 4;
            uint32_t aH[4], aL[4], bH[4], bL[4];
            LDSM4(aH, ah + ((uHiA ^ ar7) << 4));
            LDSM4(bH, bh + ((uHiB ^ br7) << 4));
            LDSM4(aL, ah + ((uLoA ^ ar7) << 4));
            LDSM4(bL, bh + ((uLoB ^ br7) << 4));
            MMA_BF16(acc[h][0], aH, bH[0], bH[1]);
            MMA_BF16(acc[h][1], aH, bH[2], bH[3]);
            MMA_BF16(acc[h][0], aH, bL[0], bL[1]);
            MMA_BF16(acc[h][1], aH, bL[2], bL[3]);
            MMA_BF16(acc[h][0], aL, bH[0], bH[1]);
            MMA_BF16(acc[h][1], aL, bH[2], bH[3]);
        }
    }

    float w1r[8][4], b1r[8], w2r[4][8], b2r[4];
#pragma unroll
    for (int e = 0; e < 8; e++) {
        b1r[e] = __ldg(&b1[e]);
#pragma unroll
        for (int h = 0; h < 4; h++) w1r[e][h] = __ldg(&w1[e * 4 + h]);
    }
#pragma unroll
    for (int h = 0; h < 4; h++) {
        b2r[h] = __ldg(&b2[h]);
#pragma unroll
        for (int e = 0; e < 8; e++) w2r[h][e] = __ldg(&w2[h * 8 + e]);
    }

    const float4* rpe_s = (const float4*)(sm + SM_RPE);
    const int* qp_s = (const int*)(sm + SM_QP);
    const int* kp_s = (const int*)(sm + SM_KP);

    const int krow0 = wk0 + (lane >> 2);
    const int qcol0 = wq0 + (lane & 3) * 2;
    const int kg0 = ktile * 64;
    const int qg0 = qtile * 32;

    int kv[2], qv[2][2];
#pragma unroll
    for (int kr = 0; kr < 2; kr++) kv[kr] = kp_s[krow0 + kr * 8];
#pragma unroll
    for (int j = 0; j < 2; j++)
#pragma unroll
        for (int qc = 0; qc < 2; qc++) qv[j][qc] = qp_s[qcol0 + j * 8 + qc];

#pragma unroll
    for (int j = 0; j < 2; j++) {
#pragma unroll
        for (int kr = 0; kr < 2; kr++) {
#pragma unroll
            for (int qc = 0; qc < 2; qc++) {
                const int c = kr * 2 + qc;
                int rel = qv[j][qc] - kv[kr];
                rel = rel < -128 ? -128 : (rel > 128 ? 128 : rel);
                float4 rp = rpe_s[rel + 128];
                float rph[4] = {rp.x, rp.y, rp.z, rp.w};

                float sh[4], gh[4];
#pragma unroll
                for (int h = 0; h < 4; h++) {
                    sh[h] = fmaxf(acc[h][j][c] + rph[h], 0.f);
                    gh[h] = acc[4 + h][j][c] + rph[h];
                }
                float zh[4] = {b2r[0], b2r[1], b2r[2], b2r[3]};
#pragma unroll
                for (int e = 0; e < 8; e++) {
                    float t = b1r[e];
#pragma unroll
                    for (int h = 0; h < 4; h++) t = fmaf(gh[h], w1r[e][h], t);
                    t = fmaxf(t, 0.f);
#pragma unroll
                    for (int h = 0; h < 4; h++) zh[h] = fmaf(t, w2r[h][e], zh[h]);
                }
                float o = 0.f;
#pragma unroll
                for (int h = 0; h < 4; h++) {
                    float g = __fdividef(1.f, 1.f + __expf(-zh[h]));
                    o = fmaf(sh[h], g, o);
                }
                const int qg = qg0 + qcol0 + j * 8 + qc;
                const int kg = kg0 + krow0 + kr * 8;
                out[(size_t)qg * NK + kg] = o;
            }
        }
    }
}

// ---------------------------------------------------------------------------
extern "C" void kernel_launch(void* const* d_in, const int* in_sizes, int n_in,
                              void* d_out, int out_size)
{
    const float* query = (const float*)d_in[0];
    const float* key   = (const float*)d_in[1];
    const int*   qpos  = (const int*)  d_in[2];
    const int*   kpos  = (const int*)  d_in[3];
    const float* Wq    = (const float*)d_in[4];
    const float* Wk    = (const float*)d_in[5];
    const float* rpe   = (const float*)d_in[6];
    const float* w1    = (const float*)d_in[7];
    const float* b1    = (const float*)d_in[8];
    const float* w2    = (const float*)d_in[9];
    const float* b2    = (const float*)d_in[10];
    float* out = (float*)d_out;
    (void)in_sizes; (void)n_in; (void)out_size;

    cudaFuncSetAttribute(proj_mma,
                         cudaFuncAttributeMaxDynamicSharedMemorySize, PROJ_SMEM);
    cudaFuncSetAttribute(rpe_gate_mma,
                         cudaFuncAttributeMaxDynamicSharedMemorySize, SM_TOT);

    convert_split<<<3328, 256>>>(query, key, Wq, Wk);
    proj_mma<<<384, 256, PROJ_SMEM>>>();
    rpe_gate_mma<<<dim3(NK / 64, NQ / 32), 256, SM_TOT>>>(
        qpos, kpos, rpe, w1, b1, w2, b2, out);
}

// round 15
// speedup vs baseline: 1.1720x; 1.0092x over previous
#include <cuda_runtime.h>
#include <cuda_bf16.h>
#include <cstdint>

#define NQ 2048
#define NK 4096
#define DIMK 1024

// Split-bf16 operand tiles for the main kernel: per (pos, head) one 128B row =
// hi d0..31 | lo d0..31, 16B units permuted u ^= (pos & 7).
__device__ uint4 g_K_sw[NK * 8 * 8];   // (pos*8+head)*8 units
__device__ uint4 g_Q_sw[NQ * 8 * 8];

// Pre-converted projection operands, chunked layout: [chunk 0..31][row][128B row]
__device__ uint4 g_AC[32 * 6144 * 8];   // 25.2 MB
__device__ uint4 g_WC[32 * 512 * 8];    // 2 MB

#define LDSM4(r, addr) \
    asm volatile("ldmatrix.sync.aligned.m8n8.x4.shared.b16 {%0,%1,%2,%3}, [%4];" \
        : "=r"((r)[0]),"=r"((r)[1]),"=r"((r)[2]),"=r"((r)[3]) : "r"(addr))

#define MMA_BF16(accp, a, b0, b1) \
    asm volatile("mma.sync.aligned.m16n8k16.row.col.f32.bf16.bf16.f32 " \
        "{%0,%1,%2,%3}, {%4,%5,%6,%7}, {%8,%9}, {%0,%1,%2,%3};" \
        : "+f"((accp)[0]),"+f"((accp)[1]),"+f"((accp)[2]),"+f"((accp)[3]) \
        : "r"((a)[0]),"r"((a)[1]),"r"((a)[2]),"r"((a)[3]), "r"(b0),"r"(b1))

static __device__ __forceinline__ uint32_t smem_u32(const void* p) {
    uint32_t a;
    asm("{ .reg .u64 t; cvta.to.shared.u64 t, %1; cvt.u32.u64 %0, t; }"
        : "=r"(a) : "l"(p));
    return a;
}

static __device__ __forceinline__ void split2(float f0, float f1,
                                              uint32_t& hv, uint32_t& lv) {
    __nv_bfloat16 h0 = __float2bfloat16(f0);
    __nv_bfloat16 h1 = __float2bfloat16(f1);
    __nv_bfloat16 l0 = __float2bfloat16(f0 - __bfloat162float(h0));
    __nv_bfloat16 l1 = __float2bfloat16(f1 - __bfloat162float(h1));
    hv = (uint32_t)__bfloat16_as_ushort(h0) | ((uint32_t)__bfloat16_as_ushort(h1) << 16);
    lv = (uint32_t)__bfloat16_as_ushort(l0) | ((uint32_t)__bfloat16_as_ushort(l1) << 16);
}

// ---------------------------------------------------------------------------
// Convert kernel (R14, unchanged): fp32 -> bf16 hi|lo split chunks.
// ---------------------------------------------------------------------------
__global__ __launch_bounds__(256) void convert_split(
    const float* __restrict__ Qin, const float* __restrict__ Kin,
    const float* __restrict__ Wq,  const float* __restrict__ Wk)
{
    const int t = blockIdx.x * 256 + threadIdx.x;
    const int r = t >> 7;
    const int rem = t & 127;
    const int ch = rem >> 2;
    const int g  = rem & 3;

    const float* src;
    unsigned char* dstbase;
    int rows, lr;
    if (r < 6144) {
        lr = r;
        src = (r < 2048) ? (Qin + (size_t)r * DIMK)
                         : (Kin + (size_t)(r - 2048) * DIMK);
        dstbase = (unsigned char*)g_AC; rows = 6144;
    } else {
        lr = r - 6144;
        src = (lr < 256) ? (Wq + (size_t)lr * DIMK)
                         : (Wk + (size_t)(lr - 256) * DIMK);
        dstbase = (unsigned char*)g_WC; rows = 512;
    }

    const float* p = src + ch * 32 + g * 8;
    float4 v0 = *(const float4*)p;
    float4 v1 = *(const float4*)(p + 4);

    uint32_t h[4], l[4];
    split2(v0.x, v0.y, h[0], l[0]);
    split2(v0.z, v0.w, h[1], l[1]);
    split2(v1.x, v1.y, h[2], l[2]);
    split2(v1.z, v1.w, h[3], l[3]);

    const int r7 = lr & 7;
    unsigned char* rowb = dstbase + ((size_t)ch * rows + lr) * 128;
    *(uint4*)(rowb + ((g ^ r7) << 4))       = make_uint4(h[0], h[1], h[2], h[3]);
    *(uint4*)(rowb + (((g + 4) ^ r7) << 4)) = make_uint4(l[0], l[1], l[2], l[3]);
}

// ---------------------------------------------------------------------------
// Projection (R14, unchanged): pure-consumer GEMM, cp.async 4-stage pipeline.
// ---------------------------------------------------------------------------
#define PSTAGE 16384
#define PROJ_SMEM 65536
#define STAGE_PITCH 144

__global__ __launch_bounds__(256, 3) void proj_mma()
{
    extern __shared__ char smem_all[];

    const int mtile = blockIdx.x >> 2;
    const int ntile = blockIdx.x & 3;
    int isQ, m0, m0row;
    if (mtile < 32) { isQ = 1; m0 = mtile * 64;        m0row = m0; }
    else            { isQ = 0; m0 = (mtile - 32) * 64; m0row = 2048 + m0; }
    const int n0 = ntile * 64;
    const int wrow = (isQ ? 0 : 256) + n0;

    const int tid  = threadIdx.x;
    const int wid  = tid >> 5;
    const int lane = tid & 31;
    const int wm = wid & 1;
    const int wn = wid >> 1;

    const uint32_t sm_u = smem_u32(smem_all);

#define PROJ_ISSUE(ch)  do {                                                   \
        const uint32_t st_ = sm_u + ((ch) & 3) * PSTAGE;                       \
        const uint4* sA_ = g_AC + ((size_t)(ch) * 6144 + m0row) * 8;           \
        const uint4* sW_ = g_WC + ((size_t)(ch) * 512  + wrow) * 8;            \
        asm volatile("cp.async.cg.shared.global [%0], [%1], 16;"               \
            :: "r"(st_ + tid * 16),          "l"(sA_ + tid)       : "memory"); \
        asm volatile("cp.async.cg.shared.global [%0], [%1], 16;"               \
            :: "r"(st_ + (tid + 256) * 16),  "l"(sA_ + tid + 256) : "memory"); \
        asm volatile("cp.async.cg.shared.global [%0], [%1], 16;"               \
            :: "r"(st_ + 8192 + tid * 16),         "l"(sW_ + tid) : "memory"); \
        asm volatile("cp.async.cg.shared.global [%0], [%1], 16;"               \
            :: "r"(st_ + 8192 + (tid + 256) * 16), "l"(sW_ + tid + 256) : "memory"); \
    } while (0)

    PROJ_ISSUE(0); asm volatile("cp.async.commit_group;");
    PROJ_ISSUE(1); asm volatile("cp.async.commit_group;");
    PROJ_ISSUE(2); asm volatile("cp.async.commit_group;");

    const int rowA0 = wm * 32 + (lane & 7) + ((lane >> 3) & 1) * 8;
    const int uaddA = (lane >> 4) & 1;
    const int rowB0 = wn * 16 + (lane & 7) + ((lane >> 4) & 1) * 8;
    const int uaddB = (lane >> 3) & 1;
    const int ar7 = rowA0 & 7;
    const int br7 = rowB0 & 7;

    float acc[2][2][4];
#pragma unroll
    for (int mm = 0; mm < 2; mm++)
#pragma unroll
        for (int nn = 0; nn < 2; nn++)
#pragma unroll
            for (int c = 0; c < 4; c++) acc[mm][nn][c] = 0.f;

    for (int ch = 0; ch < 32; ch++) {
        asm volatile("cp.async.wait_group 2;");
        __syncthreads();
        if (ch + 3 < 32) { PROJ_ISSUE(ch + 3); }
        asm volatile("cp.async.commit_group;");

        const uint32_t aB = sm_u + (ch & 3) * PSTAGE;
        const uint32_t bB = aB + 8192;
#pragma unroll
        for (int s = 0; s < 2; s++) {
            const int uHA = s * 2 + uaddA, uLA = uHA + 4;
            const int uHB = s * 2 + uaddB, uLB = uHB + 4;
            uint32_t aH0[4], aH1[4], aL0[4], aL1[4], bH[4], bL[4];
            LDSM4(aH0, aB + rowA0 * 128        + ((uHA ^ ar7) << 4));
            LDSM4(aH1, aB + (rowA0 + 16) * 128 + ((uHA ^ ar7) << 4));
            LDSM4(bH,  bB + rowB0 * 128        + ((uHB ^ br7) << 4));
            LDSM4(aL0, aB + rowA0 * 128        + ((uLA ^ ar7) << 4));
            LDSM4(aL1, aB + (rowA0 + 16) * 128 + ((uLA ^ ar7) << 4));
            LDSM4(bL,  bB + rowB0 * 128        + ((uLB ^ br7) << 4));

            MMA_BF16(acc[0][0], aH0, bH[0], bH[1]); MMA_BF16(acc[0][1], aH0, bH[2], bH[3]);
            MMA_BF16(acc[1][0], aH1, bH[0], bH[1]); MMA_BF16(acc[1][1], aH1, bH[2], bH[3]);
            MMA_BF16(acc[0][0], aH0, bL[0], bL[1]); MMA_BF16(acc[0][1], aH0, bL[2], bL[3]);
            MMA_BF16(acc[1][0], aH1, bL[0], bL[1]); MMA_BF16(acc[1][1], aH1, bL[2], bL[3]);
            MMA_BF16(acc[0][0], aL0, bH[0], bH[1]); MMA_BF16(acc[0][1], aL0, bH[2], bH[3]);
            MMA_BF16(acc[1][0], aL1, bH[0], bH[1]); MMA_BF16(acc[1][1], aL1, bH[2], bH[3]);
        }
    }
    asm volatile("cp.async.wait_group 0;");
    __syncthreads();

#pragma unroll
    for (int mm = 0; mm < 2; mm++) {
#pragma unroll
        for (int nn = 0; nn < 2; nn++) {
            const int local_n = wn * 16 + nn * 8 + (lane & 3) * 2;
            const int head_local = local_n >> 5;
            const int d0 = local_n & 31;
            const int u = d0 >> 3;
            const int within = (d0 & 7) * 2;
#pragma unroll
            for (int rr = 0; rr < 2; rr++) {
                const int local_m = wm * 32 + mm * 16 + (lane >> 2) + rr * 8;
                uint32_t hv, lv;
                split2(acc[mm][nn][rr * 2], acc[mm][nn][rr * 2 + 1], hv, lv);
                char* rb = smem_all + (head_local * 64 + local_m) * STAGE_PITCH;
                const int r7 = local_m & 7;
                *(uint32_t*)(rb + ((u ^ r7) << 4) + within)       = hv;
                *(uint32_t*)(rb + (((u + 4) ^ r7) << 4) + within) = lv;
            }
        }
    }
    __syncthreads();

    unsigned char* gbase = (unsigned char*)(isQ ? g_Q_sw : g_K_sw);
#pragma unroll
    for (int pass = 0; pass < 4; pass++) {
        const int row = (tid >> 3) + pass * 32;
        const int unit = tid & 7;
        const int head_local = row >> 6;
        const int local_m = row & 63;
        const int m = m0 + local_m;
        const int head = (n0 >> 5) + head_local;
        uint4 v = *(uint4*)(smem_all + row * STAGE_PITCH + unit * 16);
        *(uint4*)(gbase + (size_t)(m * 8 + head) * 128 + unit * 16) = v;
    }
}

// ---------------------------------------------------------------------------
// Main kernel: CTA 64k x 32q, 8 warps, warp 16k x 16q — SAME tile/traffic as
// the 97.8us config, but staged PER HEAD via a 4-deep cp.async pipeline
// (12KB/stage, 48KB total) -> 3 CTAs/SM and load/compute overlap.
// ---------------------------------------------------------------------------
#define MSTAGE   12288     // 8KB K (64 rows) + 4KB Q (32 rows) per head
#define SM_RPE   49152     // 4 * 12288
#define SM_QP    53264     // SM_RPE + 4112
#define SM_KP    53392     // + 32*4
#define SM_TOT   53648     // + 64*4

__global__ __launch_bounds__(256, 3) void rpe_gate_mma(
    const int*   __restrict__ qpos, const int* __restrict__ kpos,
    const float* __restrict__ rpe_table,
    const float* __restrict__ w1, const float* __restrict__ b1,
    const float* __restrict__ w2, const float* __restrict__ b2,
    float* __restrict__ out)
{
    extern __shared__ char sm[];
    const uint32_t sb = smem_u32(sm);

    const int tid  = threadIdx.x;
    const int wid  = tid >> 5;
    const int lane = tid & 31;
    const int ktile = blockIdx.x;
    const int qtile = blockIdx.y;

    // K head-h rows: uint4 index ((ktile*64 + r)*8 + h)*8 + u  (r stride = 64)
    // Q head-h rows: ((qtile*32 + r)*8 + h)*8 + u
    const int lr_k = tid >> 3;        // 0..31 (+32 second half)
    const int lu   = tid & 7;
#define MAIN_ISSUE(h) do {                                                     \
        const uint32_t st_ = sb + ((h) & 3) * MSTAGE;                          \
        const uint4* bK_ = g_K_sw + ((size_t)(ktile * 64) * 8 + (h)) * 8;      \
        const uint4* bQ_ = g_Q_sw + ((size_t)(qtile * 32) * 8 + (h)) * 8;      \
        asm volatile("cp.async.cg.shared.global [%0], [%1], 16;"               \
            :: "r"(st_ + tid * 16),                                            \
               "l"(bK_ + (size_t)lr_k * 64 + lu) : "memory");                  \
        asm volatile("cp.async.cg.shared.global [%0], [%1], 16;"               \
            :: "r"(st_ + (tid + 256) * 16),                                    \
               "l"(bK_ + (size_t)(lr_k + 32) * 64 + lu) : "memory");           \
        asm volatile("cp.async.cg.shared.global [%0], [%1], 16;"               \
            :: "r"(st_ + 8192 + tid * 16),                                     \
               "l"(bQ_ + (size_t)lr_k * 64 + lu) : "memory");                  \
    } while (0)

    MAIN_ISSUE(0); asm volatile("cp.async.commit_group;");
    MAIN_ISSUE(1); asm volatile("cp.async.commit_group;");
    MAIN_ISSUE(2); asm volatile("cp.async.commit_group;");

    // rpe + positions via normal loads (overlap pipeline fill)
    for (int i = tid; i < 257; i += 256)
        *(float4*)(sm + SM_RPE + i * 16) = ((const float4*)rpe_table)[i];
    if (tid < 32) *(int*)(sm + SM_QP + tid * 4) = qpos[qtile * 32 + tid];
    if (tid < 64) *(int*)(sm + SM_KP + tid * 4) = kpos[ktile * 64 + tid];

    const int wk0 = (wid & 3) * 16;
    const int wq0 = (wid >> 2) * 16;

    const int rowA = wk0 + (lane & 7) + ((lane >> 3) & 1) * 8;
    const int uaddA = (lane >> 4) & 1;
    const int rowB = wq0 + (lane & 7) + ((lane >> 4) & 1) * 8;
    const int uaddB = (lane >> 3) & 1;
    const int ar7 = rowA & 7;
    const int br7 = rowB & 7;

    float acc[8][2][4];
#pragma unroll
    for (int h = 0; h < 8; h++)
#pragma unroll
        for (int j = 0; j < 2; j++)
#pragma unroll
            for (int c = 0; c < 4; c++) acc[h][j][c] = 0.f;

#pragma unroll
    for (int h = 0; h < 8; h++) {
        asm volatile("cp.async.wait_group 2;");
        __syncthreads();
        if (h + 3 < 8) { MAIN_ISSUE(h + 3); }
        asm volatile("cp.async.commit_group;");

        const uint32_t stg = sb + (h & 3) * MSTAGE;
        const uint32_t ah = stg + rowA * 128;
        const uint32_t bh = stg + 8192 + rowB * 128;
#pragma unroll
        for (int s = 0; s < 2; s++) {
            const int uHiA = s * 2 + uaddA, uLoA = uHiA + 4;
            const int uHiB = s * 2 + uaddB, uLoB = uHiB + 4;
            uint32_t aH[4], aL[4], bH[4], bL[4];
            LDSM4(aH, ah + ((uHiA ^ ar7) << 4));
            LDSM4(bH, bh + ((uHiB ^ br7) << 4));
            LDSM4(aL, ah + ((uLoA ^ ar7) << 4));
            LDSM4(bL, bh + ((uLoB ^ br7) << 4));
            MMA_BF16(acc[h][0], aH, bH[0], bH[1]);
            MMA_BF16(acc[h][1], aH, bH[2], bH[3]);
            MMA_BF16(acc[h][0], aH, bL[0], bL[1]);
            MMA_BF16(acc[h][1], aH, bL[2], bL[3]);
            MMA_BF16(acc[h][0], aL, bH[0], bH[1]);
            MMA_BF16(acc[h][1], aL, bH[2], bH[3]);
        }
    }
    asm volatile("cp.async.wait_group 0;");

    // ---- Epilogue (identical math to the 97.8us version) ----
    float w1r[8][4], b1r[8], w2r[4][8], b2r[4];
#pragma unroll
    for (int e = 0; e < 8; e++) {
        b1r[e] = __ldg(&b1[e]);
#pragma unroll
        for (int h = 0; h < 4; h++) w1r[e][h] = __ldg(&w1[e * 4 + h]);
    }
#pragma unroll
    for (int h = 0; h < 4; h++) {
        b2r[h] = __ldg(&b2[h]);
#pragma unroll
        for (int e = 0; e < 8; e++) w2r[h][e] = __ldg(&w2[h * 8 + e]);
    }

    const float4* rpe_s = (const float4*)(sm + SM_RPE);
    const int* qp_s = (const int*)(sm + SM_QP);
    const int* kp_s = (const int*)(sm + SM_KP);

    const int krow0 = wk0 + (lane >> 2);
    const int qcol0 = wq0 + (lane & 3) * 2;
    const int kg0 = ktile * 64;
    const int qg0 = qtile * 32;

    int kv[2], qv[2][2];
#pragma unroll
    for (int kr = 0; kr < 2; kr++) kv[kr] = kp_s[krow0 + kr * 8];
#pragma unroll
    for (int j = 0; j < 2; j++)
#pragma unroll
        for (int qc = 0; qc < 2; qc++) qv[j][qc] = qp_s[qcol0 + j * 8 + qc];

#pragma unroll
    for (int j = 0; j < 2; j++) {
#pragma unroll
        for (int kr = 0; kr < 2; kr++) {
#pragma unroll
            for (int qc = 0; qc < 2; qc++) {
                const int c = kr * 2 + qc;
                int rel = qv[j][qc] - kv[kr];
                rel = rel < -128 ? -128 : (rel > 128 ? 128 : rel);
                float4 rp = rpe_s[rel + 128];
                float rph[4] = {rp.x, rp.y, rp.z, rp.w};

                float sh[4], gh[4];
#pragma unroll
                for (int h = 0; h < 4; h++) {
                    sh[h] = fmaxf(acc[h][j][c] + rph[h], 0.f);
                    gh[h] = acc[4 + h][j][c] + rph[h];
                }
                float zh[4] = {b2r[0], b2r[1], b2r[2], b2r[3]};
#pragma unroll
                for (int e = 0; e < 8; e++) {
                    float t = b1r[e];
#pragma unroll
                    for (int h = 0; h < 4; h++) t = fmaf(gh[h], w1r[e][h], t);
                    t = fmaxf(t, 0.f);
#pragma unroll
                    for (int h = 0; h < 4; h++) zh[h] = fmaf(t, w2r[h][e], zh[h]);
                }
                float o = 0.f;
#pragma unroll
                for (int h = 0; h < 4; h++) {
                    float g = __fdividef(1.f, 1.f + __expf(-zh[h]));
                    o = fmaf(sh[h], g, o);
                }
                const int qg = qg0 + qcol0 + j * 8 + qc;
                const int kg = kg0 + krow0 + kr * 8;
                out[(size_t)qg * NK + kg] = o;
            }
        }
    }
}

// ---------------------------------------------------------------------------
extern "C" void kernel_launch(void* const* d_in, const int* in_sizes, int n_in,
                              void* d_out, int out_size)
{
    const float* query = (const float*)d_in[0];
    const float* key   = (const float*)d_in[1];
    const int*   qpos  = (const int*)  d_in[2];
    const int*   kpos  = (const int*)  d_in[3];
    const float* Wq    = (const float*)d_in[4];
    const float* Wk    = (const float*)d_in[5];
    const float* rpe   = (const float*)d_in[6];
    const float* w1    = (const float*)d_in[7];
    const float* b1    = (const float*)d_in[8];
    const float* w2    = (const float*)d_in[9];
    const float* b2    = (const float*)d_in[10];
    float* out = (float*)d_out;
    (void)in_sizes; (void)n_in; (void)out_size;

    cudaFuncSetAttribute(proj_mma,
                         cudaFuncAttributeMaxDynamicSharedMemorySize, PROJ_SMEM);
    cudaFuncSetAttribute(rpe_gate_mma,
                         cudaFuncAttributeMaxDynamicSharedMemorySize, SM_TOT);

    convert_split<<<3328, 256>>>(query, key, Wq, Wk);
    proj_mma<<<384, 256, PROJ_SMEM>>>();
    rpe_gate_mma<<<dim3(NK / 64, NQ / 32), 256, SM_TOT>>>(
        qpos, kpos, rpe, w1, b1, w2, b2, out);
}